// round 2
// baseline (speedup 1.0000x reference)
#include <cuda_runtime.h>
#include <math.h>
#include <float.h>

#define NCH 85
#define NTC 6
#define SS  (52 * 52)
#define LOG2E 1.44269504088896340736f

// scratch: [0]=sum_noobj_bce [1]=cnt_noobj [2]=sum_obj_bce [3]=cnt_obj
//          [4]=sum_ciou [5]=sum_box [6]=sum_cls
__device__ double g_acc[7];

__global__ void zero_acc_kernel() {
    if (threadIdx.x < 7) g_acc[threadIdx.x] = 0.0;
}

__device__ __forceinline__ float warp_max(float v) {
#pragma unroll
    for (int o = 16; o; o >>= 1) v = fmaxf(v, __shfl_xor_sync(0xffffffffu, v, o));
    return v;
}
__device__ __forceinline__ float warp_sum(float v) {
#pragma unroll
    for (int o = 16; o; o >>= 1) v += __shfl_xor_sync(0xffffffffu, v, o);
    return v;
}

// FFMA-pipe exp2 for x in [-30, 0]: magic-number round-to-nearest + degree-5 poly.
__device__ __forceinline__ float fast_exp2(float x) {
    float r  = x + 12582912.0f;                     // 1.5 * 2^23
    int   ik = __float_as_int(r) - 0x4B400000;      // round(x)
    float fk = r - 12582912.0f;                     // (float)round(x), no I2F
    float f  = x - fk;                              // f in [-0.5, 0.5]
    float p  = 1.3333558e-3f;                       // ln2^5/120
    p = fmaf(p, f, 9.6181291e-3f);                  // ln2^4/24
    p = fmaf(p, f, 5.5504109e-2f);                  // ln2^3/6
    p = fmaf(p, f, 2.4022651e-1f);                  // ln2^2/2
    p = fmaf(p, f, 6.9314718e-1f);                  // ln2
    p = fmaf(p, f, 1.0f);
    return p * __int_as_float((ik + 127) << 23);
}

__device__ __forceinline__ float sigmoidf_(float x) {
    return 1.0f / (1.0f + __expf(-x));
}

__global__ __launch_bounds__(256)
void yolo_loss_kernel(const float* __restrict__ pred,
                      const float* __restrict__ tgt,
                      const float* __restrict__ anc,
                      int ncells) {
    const int lane   = threadIdx.x & 31;
    const int warp   = (blockIdx.x * blockDim.x + threadIdx.x) >> 5;
    const int nwarps = (gridDim.x * blockDim.x) >> 5;

    const float a0w = anc[0], a0h = anc[1];
    const float a1w = anc[2], a1h = anc[3];
    const float a2w = anc[4], a2h = anc[5];

    float s_noobj = 0.f, c_noobj = 0.f;
    float s_obj = 0.f, c_obj = 0.f;
    float s_ciou = 0.f, s_box = 0.f, s_cls = 0.f;

    for (int cell = warp; cell < ncells; cell += nwarps) {
        const float* p = pred + (size_t)cell * NCH;
        const float* t = tgt  + (size_t)cell * NTC;

        float v0 = __ldg(p + lane);
        float v1 = __ldg(p + 32 + lane);
        float v2 = (lane < 21) ? __ldg(p + 64 + lane) : -FLT_MAX;
        float tv = (lane < 6)  ? __ldg(t + lane) : 0.0f;

        const float t0 = __shfl_sync(0xffffffffu, tv, 0);
        const float p0 = __shfl_sync(0xffffffffu, v0, 0);

        if (t0 == 0.0f) {
            // no-object: bce(p0, 0)
            s_noobj += fmaxf(p0, 0.0f) + log1pf(__expf(-fabsf(p0)));
            c_noobj += 1.0f;
        }
        if (t0 == 1.0f) {
            c_obj += 1.0f;
            const float p1 = __shfl_sync(0xffffffffu, v0, 1);
            const float p2 = __shfl_sync(0xffffffffu, v0, 2);
            const float p3 = __shfl_sync(0xffffffffu, v0, 3);
            const float p4 = __shfl_sync(0xffffffffu, v0, 4);
            const float t1 = __shfl_sync(0xffffffffu, tv, 1);
            const float t2 = __shfl_sync(0xffffffffu, tv, 2);
            const float t3 = __shfl_sync(0xffffffffu, tv, 3);
            const float t4 = __shfl_sync(0xffffffffu, tv, 4);
            const float t5 = __shfl_sync(0xffffffffu, tv, 5);

            const int a = (cell / SS) % 3;
            const float aw = (a == 0) ? a0w : ((a == 1) ? a1w : a2w);
            const float ah = (a == 0) ? a0h : ((a == 1) ? a1h : a2h);

            const float sx = sigmoidf_(p1);
            const float sy = sigmoidf_(p2);
            const float bw = __expf(p3) * aw;
            const float bh = __expf(p4) * ah;

            // ---- midpoint IoU (for object bce target) ----
            const float b1x1 = sx - 0.5f * bw, b1x2 = sx + 0.5f * bw;
            const float b1y1 = sy - 0.5f * bh, b1y2 = sy + 0.5f * bh;
            const float b2x1 = t1 - 0.5f * t3, b2x2 = t1 + 0.5f * t3;
            const float b2y1 = t2 - 0.5f * t4, b2y2 = t2 + 0.5f * t4;
            const float iw = fmaxf(fminf(b1x2, b2x2) - fmaxf(b1x1, b2x1), 0.0f);
            const float ih = fmaxf(fminf(b1y2, b2y2) - fmaxf(b1y1, b2y1), 0.0f);
            const float inter = iw * ih;
            const float area1 = fabsf(bw * bh);
            const float area2 = fabsf(t3 * t4);
            const float iou_m = inter / (area1 + area2 - inter + 1e-6f);

            s_obj += fmaxf(p0, 0.0f) - p0 * iou_m + log1pf(__expf(-fabsf(p0)));

            // ---- CIoU on xyxy of same boxes ----
            const float uni  = bw * bh + t3 * t4 - inter;
            const float iou  = inter / (uni + 1e-7f);
            const float cw   = fmaxf(b1x2, b2x2) - fminf(b1x1, b2x1);
            const float chh  = fmaxf(b1y2, b2y2) - fminf(b1y1, b2y1);
            const float diag = cw * cw + chh * chh + 1e-7f;
            const float dx   = sx - t1;
            const float dy   = sy - t2;
            const float diou = 1.0f - iou + (dx * dx + dy * dy) / diag;
            const float dat  = atanf(t3 / (t4 + 1e-7f)) - atanf(bw / (bh + 1e-7f));
            const float vv   = 0.40528473456f * dat * dat;   // 4/pi^2
            const float alpha = vv / (1.0f - iou + vv + 1e-7f);
            s_ciou += diou + alpha * vv;

            // ---- box regression loss ----
            const float lw = __logf(1e-16f + t3 / aw);
            const float lh = __logf(1e-16f + t4 / ah);
            const float d1 = sx - t1, d2 = sy - t2, d3 = p3 - lw, d4 = p4 - lh;
            s_box += d1 * d1 + d2 * d2 + d3 * d3 + d4 * d4;

            // ---- class NLL via log-softmax over channels 5..84 ----
            const float c0 = (lane >= 5) ? v0 : -FLT_MAX;
            const float m  = warp_max(fmaxf(fmaxf(c0, v1), v2));
            float e = 0.0f;
            if (lane >= 5) e += fast_exp2(fmaxf((v0 - m) * LOG2E, -30.0f));
            e += fast_exp2(fmaxf((v1 - m) * LOG2E, -30.0f));
            if (lane < 21) e += fast_exp2(fmaxf((v2 - m) * LOG2E, -30.0f));
            const float Z = warp_sum(e);

            const int lch = 5 + (int)t5;
            float cand = -FLT_MAX;
            if (lane == lch)      cand = v0;
            if (lane + 32 == lch) cand = v1;
            if (lane + 64 == lch) cand = v2;
            const float xl = warp_max(cand);

            s_cls += (m + __logf(Z)) - xl;
        }
    }

    // block reduction (values are warp-uniform; lane 0 contributes)
    __shared__ float sm[7][8];
    const int wib = threadIdx.x >> 5;
    if (lane == 0) {
        sm[0][wib] = s_noobj; sm[1][wib] = c_noobj;
        sm[2][wib] = s_obj;   sm[3][wib] = c_obj;
        sm[4][wib] = s_ciou;  sm[5][wib] = s_box;  sm[6][wib] = s_cls;
    }
    __syncthreads();
    if (threadIdx.x < 7) {
        float s = 0.f;
        const int nw = blockDim.x >> 5;
        for (int w = 0; w < nw; w++) s += sm[threadIdx.x][w];
        atomicAdd(&g_acc[threadIdx.x], (double)s);
    }
}

__global__ void finalize_kernel(float* out) {
    const double cobj = fmax(g_acc[3], 1.0);
    const double noobj_l = g_acc[0] / fmax(g_acc[1], 1.0);
    const double obj_l   = g_acc[2] / cobj;
    const double ciou_l  = g_acc[4] / cobj;
    const double box_l   = (g_acc[5] / cobj) * 0.25;
    const double cls_l   = g_acc[6] / cobj;
    out[0] = (float)(10.0 * box_l + 10.0 * obj_l + 1.0 * noobj_l + 1.0 * cls_l + ciou_l);
}

extern "C" void kernel_launch(void* const* d_in, const int* in_sizes, int n_in,
                              void* d_out, int out_size) {
    // robust input mapping: anchors has 6 elems; predictions is the largest
    int ip = 0, it = 1, ia = 2;
    long best = -1;
    for (int i = 0; i < n_in; i++) {
        if (in_sizes[i] == 6) ia = i;
        if ((long)in_sizes[i] > best) { best = in_sizes[i]; ip = i; }
    }
    for (int i = 0; i < n_in; i++) if (i != ip && i != ia) it = i;

    const float* pred = (const float*)d_in[ip];
    const float* tgt  = (const float*)d_in[it];
    const float* anc  = (const float*)d_in[ia];
    const int ncells  = in_sizes[ip] / NCH;

    zero_acc_kernel<<<1, 32>>>();
    yolo_loss_kernel<<<1184, 256>>>(pred, tgt, anc, ncells);
    finalize_kernel<<<1, 1>>>((float*)d_out);
}

// round 5
// speedup vs baseline: 1.1667x; 1.1667x over previous
#include <cuda_runtime.h>
#include <math.h>
#include <float.h>

#define NCH 85
#define NTC 6
#define SS  (52 * 52)
#define LOG2E 1.44269504088896340736f
#define NBLK 1184

// accumulators: [0]=sum_noobj [1]=cnt_noobj [2]=sum_obj [3]=cnt_obj
//               [4]=sum_ciou [5]=sum_box [6]=sum_cls
// zero-initialized at module load; finalize_kernel resets to zero every run,
// so every graph replay starts from a clean state.
__device__ double g_acc[7];

__device__ __forceinline__ float warp_max(float v) {
#pragma unroll
    for (int o = 16; o; o >>= 1) v = fmaxf(v, __shfl_xor_sync(0xffffffffu, v, o));
    return v;
}
__device__ __forceinline__ float warp_sum(float v) {
#pragma unroll
    for (int o = 16; o; o >>= 1) v += __shfl_xor_sync(0xffffffffu, v, o);
    return v;
}

// FFMA-pipe exp2 for x in [-30, 0]: magic-number round + degree-5 poly.
__device__ __forceinline__ float fast_exp2(float x) {
    float r  = x + 12582912.0f;                 // 1.5 * 2^23
    int   ik = __float_as_int(r) - 0x4B400000;
    float fk = r - 12582912.0f;
    float f  = x - fk;                          // f in [-0.5, 0.5]
    float p  = 1.3333558e-3f;
    p = fmaf(p, f, 9.6181291e-3f);
    p = fmaf(p, f, 5.5504109e-2f);
    p = fmaf(p, f, 2.4022651e-1f);
    p = fmaf(p, f, 6.9314718e-1f);
    p = fmaf(p, f, 1.0f);
    return p * __int_as_float((ik + 127) << 23);
}

__device__ __forceinline__ float sigmoidf_(float x) {
    return 1.0f / (1.0f + __expf(-x));
}

__global__ __launch_bounds__(256)
void yolo_loss_kernel(const float* __restrict__ pred,
                      const float* __restrict__ tgt,
                      const float* __restrict__ anc,
                      int ncells) {
    const int lane   = threadIdx.x & 31;
    const int gwarp  = (blockIdx.x * blockDim.x + threadIdx.x) >> 5;
    const int nwarps = (gridDim.x * blockDim.x) >> 5;

    const float a0w = __ldg(anc + 0), a0h = __ldg(anc + 1);
    const float a1w = __ldg(anc + 2), a1h = __ldg(anc + 3);
    const float a2w = __ldg(anc + 4), a2h = __ldg(anc + 5);

    float s_noobj = 0.f, c_noobj = 0.f;
    float s_obj = 0.f, c_obj = 0.f;
    float s_ciou = 0.f, s_box = 0.f, s_cls = 0.f;

    for (int base = gwarp; base < ncells; base += 4 * nwarps) {
        float2 t01[4];
        float  p0v[4];
        int    cells[4];
#pragma unroll
        for (int j = 0; j < 4; j++) {
            const int c = base + j * nwarps;
            cells[j] = c;
            if (c < ncells) {
                t01[j] = __ldg((const float2*)(tgt + (size_t)c * NTC)); // broadcast, 8B-aligned
                p0v[j] = __ldg(pred + (size_t)c * NCH);                 // broadcast
            } else {
                t01[j] = make_float2(-1.0f, 0.0f);                      // sentinel: skip both paths
                p0v[j] = 0.0f;
            }
        }
#pragma unroll
        for (int j = 0; j < 4; j++) {
            const float t0 = t01[j].x;
            const float p0 = p0v[j];

            if (t0 == 0.0f) {
                // noobj: bce(p0, 0) = max(p0,0) + log(1 + exp(-|p0|))
                s_noobj += fmaxf(p0, 0.0f) + __logf(1.0f + __expf(-fabsf(p0)));
                c_noobj += 1.0f;
            } else if (t0 == 1.0f) {
                c_obj += 1.0f;
                const int cell = cells[j];
                const float* p = pred + (size_t)cell * NCH;
                const float* t = tgt  + (size_t)cell * NTC;

                // full row loads only for obj cells (~15%)
                float v0 = __ldg(p + lane);
                float v1 = __ldg(p + 32 + lane);
                float v2 = (lane < 21) ? __ldg(p + 64 + lane) : -FLT_MAX;
                const float2 t23 = __ldg((const float2*)(t + 2));
                const float2 t45 = __ldg((const float2*)(t + 4));

                const float t1 = t01[j].y;
                const float t2 = t23.x, t3 = t23.y;
                const float t4 = t45.x, t5 = t45.y;
                const float p1 = __shfl_sync(0xffffffffu, v0, 1);
                const float p2 = __shfl_sync(0xffffffffu, v0, 2);
                const float p3 = __shfl_sync(0xffffffffu, v0, 3);
                const float p4 = __shfl_sync(0xffffffffu, v0, 4);

                const int a = (cell / SS) % 3;
                const float aw = (a == 0) ? a0w : ((a == 1) ? a1w : a2w);
                const float ah = (a == 0) ? a0h : ((a == 1) ? a1h : a2h);

                const float sx = sigmoidf_(p1);
                const float sy = sigmoidf_(p2);
                const float bw = __expf(p3) * aw;
                const float bh = __expf(p4) * ah;

                // ---- midpoint IoU (bce target) ----
                const float b1x1 = sx - 0.5f * bw, b1x2 = sx + 0.5f * bw;
                const float b1y1 = sy - 0.5f * bh, b1y2 = sy + 0.5f * bh;
                const float b2x1 = t1 - 0.5f * t3, b2x2 = t1 + 0.5f * t3;
                const float b2y1 = t2 - 0.5f * t4, b2y2 = t2 + 0.5f * t4;
                const float iw = fmaxf(fminf(b1x2, b2x2) - fmaxf(b1x1, b2x1), 0.0f);
                const float ih = fmaxf(fminf(b1y2, b2y2) - fmaxf(b1y1, b2y1), 0.0f);
                const float inter = iw * ih;
                const float area1 = fabsf(bw * bh);
                const float area2 = fabsf(t3 * t4);
                const float iou_m = inter / (area1 + area2 - inter + 1e-6f);

                s_obj += fmaxf(p0, 0.0f) - p0 * iou_m + log1pf(__expf(-fabsf(p0)));

                // ---- CIoU ----
                const float uni  = bw * bh + t3 * t4 - inter;
                const float iou  = inter / (uni + 1e-7f);
                const float cw   = fmaxf(b1x2, b2x2) - fminf(b1x1, b2x1);
                const float chh  = fmaxf(b1y2, b2y2) - fminf(b1y1, b2y1);
                const float diag = cw * cw + chh * chh + 1e-7f;
                const float dx   = sx - t1;
                const float dy   = sy - t2;
                const float diou = 1.0f - iou + (dx * dx + dy * dy) / diag;
                const float dat  = atanf(t3 / (t4 + 1e-7f)) - atanf(bw / (bh + 1e-7f));
                const float vv   = 0.40528473456f * dat * dat;   // 4/pi^2
                const float alpha = vv / (1.0f - iou + vv + 1e-7f);
                s_ciou += diou + alpha * vv;

                // ---- box regression ----
                const float lw = __logf(1e-16f + t3 / aw);
                const float lh = __logf(1e-16f + t4 / ah);
                const float d1 = sx - t1, d2 = sy - t2, d3 = p3 - lw, d4 = p4 - lh;
                s_box += d1 * d1 + d2 * d2 + d3 * d3 + d4 * d4;

                // ---- class NLL: log-softmax over channels 5..84 ----
                const float c0 = (lane >= 5) ? v0 : -FLT_MAX;
                const float m  = warp_max(fmaxf(fmaxf(c0, v1), v2));
                float e = 0.0f;
                if (lane >= 5) e += fast_exp2(fmaxf((v0 - m) * LOG2E, -30.0f));
                e += fast_exp2(fmaxf((v1 - m) * LOG2E, -30.0f));
                if (lane < 21) e += fast_exp2(fmaxf((v2 - m) * LOG2E, -30.0f));
                const float Z = warp_sum(e);

                const int lch = 5 + (int)t5;
                float cand = -FLT_MAX;
                if (lane == lch)      cand = v0;
                if (lane + 32 == lch) cand = v1;
                if (lane + 64 == lch) cand = v2;
                const float xl = warp_max(cand);

                s_cls += (m + __logf(Z)) - xl;
            }
        }
    }

    // ---- block reduction, then one atomicAdd per metric per block ----
    __shared__ float sm[7][8];
    const int wib = threadIdx.x >> 5;
    if (lane == 0) {
        sm[0][wib] = s_noobj; sm[1][wib] = c_noobj;
        sm[2][wib] = s_obj;   sm[3][wib] = c_obj;
        sm[4][wib] = s_ciou;  sm[5][wib] = s_box;  sm[6][wib] = s_cls;
    }
    __syncthreads();
    if (threadIdx.x < 7) {
        float s = 0.f;
        const int nw = blockDim.x >> 5;
        for (int w = 0; w < nw; w++) s += sm[threadIdx.x][w];
        atomicAdd(&g_acc[threadIdx.x], (double)s);
    }
}

// Reads accumulators, writes the scalar loss, and resets state for the next
// graph replay (so kernel_launch is deterministic across replays).
__global__ void finalize_kernel(float* __restrict__ out) {
    if (threadIdx.x == 0) {
        const double cobj  = fmax(g_acc[3], 1.0);
        const double noobj = g_acc[0] / fmax(g_acc[1], 1.0);
        const double objl  = g_acc[2] / cobj;
        const double cioul = g_acc[4] / cobj;
        const double boxl  = (g_acc[5] / cobj) * 0.25;
        const double clsl  = g_acc[6] / cobj;
        out[0] = (float)(10.0 * boxl + 10.0 * objl + noobj + clsl + cioul);
#pragma unroll
        for (int i = 0; i < 7; i++) g_acc[i] = 0.0;
    }
}

extern "C" void kernel_launch(void* const* d_in, const int* in_sizes, int n_in,
                              void* d_out, int out_size) {
    int ip = 0, it = 1, ia = 2;
    long best = -1;
    for (int i = 0; i < n_in; i++) {
        if (in_sizes[i] == 6) ia = i;
        if ((long)in_sizes[i] > best) { best = in_sizes[i]; ip = i; }
    }
    for (int i = 0; i < n_in; i++) if (i != ip && i != ia) it = i;

    const float* pred = (const float*)d_in[ip];
    const float* tgt  = (const float*)d_in[it];
    const float* anc  = (const float*)d_in[ia];
    const int ncells  = in_sizes[ip] / NCH;

    yolo_loss_kernel<<<NBLK, 256>>>(pred, tgt, anc, ncells);
    finalize_kernel<<<1, 32>>>((float*)d_out);
}

// round 7
// speedup vs baseline: 1.4725x; 1.2621x over previous
#include <cuda_runtime.h>
#include <math.h>
#include <float.h>

#define NCH 85
#define NTC 6
#define SS  (52 * 52)
#define LOG2E 1.44269504088896340736f

// accumulators: [0]=sum_noobj [1]=cnt_noobj [2]=sum_obj [3]=cnt_obj
//               [4]=sum_ciou [5]=sum_box [6]=sum_cls
// zero at module load; finalize_kernel resets after each use -> replay-safe.
__device__ double g_acc[7];

__device__ __forceinline__ float warp_max(float v) {
#pragma unroll
    for (int o = 16; o; o >>= 1) v = fmaxf(v, __shfl_xor_sync(0xffffffffu, v, o));
    return v;
}
__device__ __forceinline__ float warp_sum(float v) {
#pragma unroll
    for (int o = 16; o; o >>= 1) v += __shfl_xor_sync(0xffffffffu, v, o);
    return v;
}

// FFMA-pipe exp2 for x in [-30, 0]: magic-number round + degree-5 poly.
__device__ __forceinline__ float fast_exp2(float x) {
    float r  = x + 12582912.0f;                 // 1.5 * 2^23
    int   ik = __float_as_int(r) - 0x4B400000;
    float f  = x - (r - 12582912.0f);           // f in [-0.5, 0.5]
    float p  = 1.3333558e-3f;
    p = fmaf(p, f, 9.6181291e-3f);
    p = fmaf(p, f, 5.5504109e-2f);
    p = fmaf(p, f, 2.4022651e-1f);
    p = fmaf(p, f, 6.9314718e-1f);
    p = fmaf(p, f, 1.0f);
    return p * __int_as_float((ik + 127) << 23);
}

// atan(x) for x > 0: range-reduce to [0,1], 6-term minimax (abs err ~2e-7).
__device__ __forceinline__ float fatan_pos(float x) {
    const bool big = (x > 1.0f);
    const float t = big ? __fdividef(1.0f, x) : x;
    const float s = t * t;
    float p = -1.1721200e-2f;
    p = fmaf(p, s,  5.2653322e-2f);
    p = fmaf(p, s, -1.1643287e-1f);
    p = fmaf(p, s,  1.9354346e-1f);
    p = fmaf(p, s, -3.3262347e-1f);
    p = fmaf(p, s,  9.9997726e-1f);
    const float r = t * p;
    return big ? (1.57079632679f - r) : r;
}

__device__ __forceinline__ float sigmoidf_(float x) {
    return 1.0f / (1.0f + __expf(-x));
}

__global__ __launch_bounds__(256)
void yolo_loss_kernel(const float* __restrict__ pred,
                      const float* __restrict__ tgt,
                      const float* __restrict__ anc,
                      int ncells) {
    const int lane   = threadIdx.x & 31;
    const int gwarp  = (blockIdx.x * blockDim.x + threadIdx.x) >> 5;
    const int nwarps = (gridDim.x * blockDim.x) >> 5;

    const float a0w = __ldg(anc + 0), a0h = __ldg(anc + 1);
    const float a1w = __ldg(anc + 2), a1h = __ldg(anc + 3);
    const float a2w = __ldg(anc + 4), a2h = __ldg(anc + 5);

    float s_noobj = 0.f, c_noobj = 0.f;
    float s_obj = 0.f, c_obj = 0.f;
    float s_ciou = 0.f, s_box = 0.f, s_cls = 0.f;

    for (int chunk = gwarp; chunk * 32 < ncells; chunk += nwarps) {
        const int base = chunk * 32;
        const int c    = base + lane;
        const bool valid = (c < ncells);

        // per-lane loads: 1 cell per thread, 32 cells per LDG
        const float2 t01 = valid ? __ldg((const float2*)(tgt + (size_t)c * NTC))
                                 : make_float2(-1.0f, 0.0f);
        const float  p0l = valid ? __ldg(pred + (size_t)c * NCH) : 0.0f;

        // ---- noobj: per-thread (no 32x redundancy) ----
        if (t01.x == 0.0f) {
            s_noobj += fmaxf(p0l, 0.0f) + __logf(1.0f + __expf(-fabsf(p0l)));
            c_noobj += 1.0f;
        }

        // ---- obj: compact via ballot, process warp-collectively ----
        unsigned om = __ballot_sync(0xffffffffu, t01.x == 1.0f);
        c_obj += (float)__popc(om);          // warp-uniform

        while (om) {
            const int l = __ffs(om) - 1;
            om &= om - 1;
            const int cell = base + l;
            const float p0 = __shfl_sync(0xffffffffu, p0l,   l);
            const float t1 = __shfl_sync(0xffffffffu, t01.y, l);

            const float* p = pred + (size_t)cell * NCH;
            const float* t = tgt  + (size_t)cell * NTC;

            float v0 = __ldg(p + lane);
            float v1 = __ldg(p + 32 + lane);
            float v2 = (lane < 21) ? __ldg(p + 64 + lane) : -FLT_MAX;
            const float2 t23 = __ldg((const float2*)(t + 2));
            const float2 t45 = __ldg((const float2*)(t + 4));
            const float t2 = t23.x, t3 = t23.y;
            const float t4 = t45.x, t5 = t45.y;

            const float p1 = __shfl_sync(0xffffffffu, v0, 1);
            const float p2 = __shfl_sync(0xffffffffu, v0, 2);
            const float p3 = __shfl_sync(0xffffffffu, v0, 3);
            const float p4 = __shfl_sync(0xffffffffu, v0, 4);

            const int a = (cell / SS) % 3;
            const float aw = (a == 0) ? a0w : ((a == 1) ? a1w : a2w);
            const float ah = (a == 0) ? a0h : ((a == 1) ? a1h : a2h);

            const float sx = sigmoidf_(p1);
            const float sy = sigmoidf_(p2);
            const float bw = __expf(p3) * aw;
            const float bh = __expf(p4) * ah;

            // ---- midpoint IoU (bce target) ----
            const float b1x1 = sx - 0.5f * bw, b1x2 = sx + 0.5f * bw;
            const float b1y1 = sy - 0.5f * bh, b1y2 = sy + 0.5f * bh;
            const float b2x1 = t1 - 0.5f * t3, b2x2 = t1 + 0.5f * t3;
            const float b2y1 = t2 - 0.5f * t4, b2y2 = t2 + 0.5f * t4;
            const float iw = fmaxf(fminf(b1x2, b2x2) - fmaxf(b1x1, b2x1), 0.0f);
            const float ih = fmaxf(fminf(b1y2, b2y2) - fmaxf(b1y1, b2y1), 0.0f);
            const float inter = iw * ih;
            const float area1 = fabsf(bw * bh);
            const float area2 = fabsf(t3 * t4);
            const float iou_m = inter / (area1 + area2 - inter + 1e-6f);

            s_obj += fmaxf(p0, 0.0f) - p0 * iou_m + __logf(1.0f + __expf(-fabsf(p0)));

            // ---- CIoU ----
            const float uni  = bw * bh + t3 * t4 - inter;
            const float iou  = inter / (uni + 1e-7f);
            const float cw   = fmaxf(b1x2, b2x2) - fminf(b1x1, b2x1);
            const float chh  = fmaxf(b1y2, b2y2) - fminf(b1y1, b2y1);
            const float diag = cw * cw + chh * chh + 1e-7f;
            const float dx   = sx - t1;
            const float dy   = sy - t2;
            const float diou = 1.0f - iou + (dx * dx + dy * dy) / diag;
            const float dat  = fatan_pos(t3 / (t4 + 1e-7f)) - fatan_pos(bw / (bh + 1e-7f));
            const float vv   = 0.40528473456f * dat * dat;   // 4/pi^2
            const float alpha = vv / (1.0f - iou + vv + 1e-7f);
            s_ciou += diou + alpha * vv;

            // ---- box regression ----
            const float lw = __logf(1e-16f + t3 / aw);
            const float lh = __logf(1e-16f + t4 / ah);
            const float d1 = sx - t1, d2 = sy - t2, d3 = p3 - lw, d4 = p4 - lh;
            s_box += d1 * d1 + d2 * d2 + d3 * d3 + d4 * d4;

            // ---- class NLL: log-softmax over channels 5..84 ----
            const float c0 = (lane >= 5) ? v0 : -FLT_MAX;
            const float m  = warp_max(fmaxf(fmaxf(c0, v1), v2));
            float e = 0.0f;
            if (lane >= 5) e += fast_exp2(fmaxf((v0 - m) * LOG2E, -30.0f));
            e += fast_exp2(fmaxf((v1 - m) * LOG2E, -30.0f));
            if (lane < 21) e += fast_exp2(fmaxf((v2 - m) * LOG2E, -30.0f));
            const float Z = warp_sum(e);

            // label logit via direct shfls (all lanes execute all three)
            const int lch = 5 + (int)t5;
            const float x0 = __shfl_sync(0xffffffffu, v0, lch & 31);
            const float x1 = __shfl_sync(0xffffffffu, v1, lch & 31);
            const float x2 = __shfl_sync(0xffffffffu, v2, lch & 31);
            const float xl = (lch < 32) ? x0 : ((lch < 64) ? x1 : x2);

            s_cls += (m + __logf(Z)) - xl;
        }
    }

    // ---- reductions: noobj per-thread -> warp; obj values warp-uniform ----
    s_noobj = warp_sum(s_noobj);
    c_noobj = warp_sum(c_noobj);

    __shared__ float sm[7][8];
    const int wib = threadIdx.x >> 5;
    if (lane == 0) {
        sm[0][wib] = s_noobj; sm[1][wib] = c_noobj;
        sm[2][wib] = s_obj;   sm[3][wib] = c_obj;
        sm[4][wib] = s_ciou;  sm[5][wib] = s_box;  sm[6][wib] = s_cls;
    }
    __syncthreads();
    if (threadIdx.x < 7) {
        float s = 0.f;
        const int nw = blockDim.x >> 5;
        for (int w = 0; w < nw; w++) s += sm[threadIdx.x][w];
        atomicAdd(&g_acc[threadIdx.x], (double)s);
    }
}

// Reads accumulators, writes scalar loss, resets state for the next replay.
__global__ void finalize_kernel(float* __restrict__ out) {
    if (threadIdx.x == 0) {
        const double cobj  = fmax(g_acc[3], 1.0);
        const double noobj = g_acc[0] / fmax(g_acc[1], 1.0);
        const double objl  = g_acc[2] / cobj;
        const double cioul = g_acc[4] / cobj;
        const double boxl  = (g_acc[5] / cobj) * 0.25;
        const double clsl  = g_acc[6] / cobj;
        out[0] = (float)(10.0 * boxl + 10.0 * objl + noobj + clsl + cioul);
#pragma unroll
        for (int i = 0; i < 7; i++) g_acc[i] = 0.0;
    }
}

extern "C" void kernel_launch(void* const* d_in, const int* in_sizes, int n_in,
                              void* d_out, int out_size) {
    int ip = 0, it = 1, ia = 2;
    long best = -1;
    for (int i = 0; i < n_in; i++) {
        if (in_sizes[i] == 6) ia = i;
        if ((long)in_sizes[i] > best) { best = in_sizes[i]; ip = i; }
    }
    for (int i = 0; i < n_in; i++) if (i != ip && i != ia) it = i;

    const float* pred = (const float*)d_in[ip];
    const float* tgt  = (const float*)d_in[it];
    const float* anc  = (const float*)d_in[ia];
    const int ncells  = in_sizes[ip] / NCH;

    const int nblk = (ncells + 255) / 256;   // one 32-cell chunk per warp
    yolo_loss_kernel<<<nblk, 256>>>(pred, tgt, anc, ncells);
    finalize_kernel<<<1, 32>>>((float*)d_out);
}

// round 8
// speedup vs baseline: 1.6365x; 1.1114x over previous
#include <cuda_runtime.h>
#include <math.h>
#include <float.h>

#define NCH 85
#define NTC 6
#define SS  (52 * 52)
#define LOG2E 1.44269504088896340736f
#define MAXCELLS 262144

// g_acc: [0]=sum_noobj [2]=sum_obj [4]=sum_ciou [5]=sum_box [6]=sum_cls
// zero at module load; finalize resets after each use -> replay-safe.
__device__ double g_acc[7];
__device__ int    g_nobj;             // obj-cell count (reset by finalize)
__device__ int    g_idx[MAXCELLS];    // compacted obj cell indices

__device__ __forceinline__ float warp_max(float v) {
#pragma unroll
    for (int o = 16; o; o >>= 1) v = fmaxf(v, __shfl_xor_sync(0xffffffffu, v, o));
    return v;
}
__device__ __forceinline__ float warp_sum(float v) {
#pragma unroll
    for (int o = 16; o; o >>= 1) v += __shfl_xor_sync(0xffffffffu, v, o);
    return v;
}

// FFMA-pipe exp2 for x in [-30, 0]: magic-number round + degree-5 poly.
__device__ __forceinline__ float fast_exp2(float x) {
    float r  = x + 12582912.0f;                 // 1.5 * 2^23
    int   ik = __float_as_int(r) - 0x4B400000;
    float f  = x - (r - 12582912.0f);           // f in [-0.5, 0.5]
    float p  = 1.3333558e-3f;
    p = fmaf(p, f, 9.6181291e-3f);
    p = fmaf(p, f, 5.5504109e-2f);
    p = fmaf(p, f, 2.4022651e-1f);
    p = fmaf(p, f, 6.9314718e-1f);
    p = fmaf(p, f, 1.0f);
    return p * __int_as_float((ik + 127) << 23);
}

// atan(x) for x > 0: range-reduce to [0,1], 6-term minimax (abs err ~2e-7).
__device__ __forceinline__ float fatan_pos(float x) {
    const bool big = (x > 1.0f);
    const float t = big ? __fdividef(1.0f, x) : x;
    const float s = t * t;
    float p = -1.1721200e-2f;
    p = fmaf(p, s,  5.2653322e-2f);
    p = fmaf(p, s, -1.1643287e-1f);
    p = fmaf(p, s,  1.9354346e-1f);
    p = fmaf(p, s, -3.3262347e-1f);
    p = fmaf(p, s,  9.9997726e-1f);
    const float r = t * p;
    return big ? (1.57079632679f - r) : r;
}

__device__ __forceinline__ float sigmoidf_(float x) {
    return 1.0f / (1.0f + __expf(-x));
}

// ───────────────────────────── Phase A: stream + compact ──────────────────
__global__ __launch_bounds__(256)
void scan_kernel(const float* __restrict__ pred,
                 const float* __restrict__ tgt,
                 int ncells) {
    const int lane   = threadIdx.x & 31;
    const int gwarp  = (blockIdx.x * blockDim.x + threadIdx.x) >> 5;
    const int nwarps = (gridDim.x * blockDim.x) >> 5;

    float s_noobj = 0.f;

    for (int chunk = gwarp; chunk * 32 < ncells; chunk += nwarps) {
        const int c = chunk * 32 + lane;
        const bool valid = (c < ncells);

        const float t0  = valid ? __ldg(tgt + (size_t)c * NTC) : -1.0f;
        const float p0l = valid ? __ldg(pred + (size_t)c * NCH) : 0.0f;

        // noobj: per-thread BCE(p0, 0)
        if (t0 == 0.0f)
            s_noobj += fmaxf(p0l, 0.0f) + __logf(1.0f + __expf(-fabsf(p0l)));

        // obj: compact indices
        const unsigned om = __ballot_sync(0xffffffffu, t0 == 1.0f);
        if (om) {
            int base_idx;
            if (lane == 0) base_idx = atomicAdd(&g_nobj, __popc(om));
            base_idx = __shfl_sync(0xffffffffu, base_idx, 0);
            if (t0 == 1.0f) {
                const int pos = __popc(om & ((1u << lane) - 1u));
                g_idx[base_idx + pos] = c;
            }
        }
    }

    // block-reduce s_noobj -> one atomic per block
    s_noobj = warp_sum(s_noobj);
    __shared__ float sm[8];
    const int wib = threadIdx.x >> 5;
    if (lane == 0) sm[wib] = s_noobj;
    __syncthreads();
    if (threadIdx.x == 0) {
        float s = 0.f;
        const int nw = blockDim.x >> 5;
        for (int w = 0; w < nw; w++) s += sm[w];
        atomicAdd(&g_acc[0], (double)s);
    }
}

// ───────────────────────────── Phase B: dense obj cells ───────────────────
__global__ __launch_bounds__(256)
void obj_kernel(const float* __restrict__ pred,
                const float* __restrict__ tgt,
                const float* __restrict__ anc) {
    const int lane   = threadIdx.x & 31;
    const int gwarp  = (blockIdx.x * blockDim.x + threadIdx.x) >> 5;
    const int nwarps = (gridDim.x * blockDim.x) >> 5;
    const int nobj   = g_nobj;

    const float a0w = __ldg(anc + 0), a0h = __ldg(anc + 1);
    const float a1w = __ldg(anc + 2), a1h = __ldg(anc + 3);
    const float a2w = __ldg(anc + 4), a2h = __ldg(anc + 5);

    float s_obj = 0.f, s_ciou = 0.f, s_box = 0.f, s_cls = 0.f;

    for (int i = gwarp; i < nobj; i += nwarps) {
        const int cell = g_idx[i];
        const float* p = pred + (size_t)cell * NCH;
        const float* t = tgt  + (size_t)cell * NTC;

        float v0 = __ldg(p + lane);
        float v1 = __ldg(p + 32 + lane);
        float v2 = (lane < 21) ? __ldg(p + 64 + lane) : -FLT_MAX;
        const float2 t01 = __ldg((const float2*)(t + 0));
        const float2 t23 = __ldg((const float2*)(t + 2));
        const float2 t45 = __ldg((const float2*)(t + 4));
        const float t1 = t01.y;
        const float t2 = t23.x, t3 = t23.y;
        const float t4 = t45.x, t5 = t45.y;

        const float p0 = __shfl_sync(0xffffffffu, v0, 0);
        const float p1 = __shfl_sync(0xffffffffu, v0, 1);
        const float p2 = __shfl_sync(0xffffffffu, v0, 2);
        const float p3 = __shfl_sync(0xffffffffu, v0, 3);
        const float p4 = __shfl_sync(0xffffffffu, v0, 4);

        const int a = (cell / SS) % 3;
        const float aw = (a == 0) ? a0w : ((a == 1) ? a1w : a2w);
        const float ah = (a == 0) ? a0h : ((a == 1) ? a1h : a2h);

        const float sx = sigmoidf_(p1);
        const float sy = sigmoidf_(p2);
        const float bw = __expf(p3) * aw;
        const float bh = __expf(p4) * ah;

        // ---- midpoint IoU (bce target) ----
        const float b1x1 = sx - 0.5f * bw, b1x2 = sx + 0.5f * bw;
        const float b1y1 = sy - 0.5f * bh, b1y2 = sy + 0.5f * bh;
        const float b2x1 = t1 - 0.5f * t3, b2x2 = t1 + 0.5f * t3;
        const float b2y1 = t2 - 0.5f * t4, b2y2 = t2 + 0.5f * t4;
        const float iw = fmaxf(fminf(b1x2, b2x2) - fmaxf(b1x1, b2x1), 0.0f);
        const float ih = fmaxf(fminf(b1y2, b2y2) - fmaxf(b1y1, b2y1), 0.0f);
        const float inter = iw * ih;
        const float area1 = fabsf(bw * bh);
        const float area2 = fabsf(t3 * t4);
        const float iou_m = inter / (area1 + area2 - inter + 1e-6f);

        s_obj += fmaxf(p0, 0.0f) - p0 * iou_m + __logf(1.0f + __expf(-fabsf(p0)));

        // ---- CIoU ----
        const float uni  = bw * bh + t3 * t4 - inter;
        const float iou  = inter / (uni + 1e-7f);
        const float cw   = fmaxf(b1x2, b2x2) - fminf(b1x1, b2x1);
        const float chh  = fmaxf(b1y2, b2y2) - fminf(b1y1, b2y1);
        const float diag = cw * cw + chh * chh + 1e-7f;
        const float dx   = sx - t1;
        const float dy   = sy - t2;
        const float diou = 1.0f - iou + (dx * dx + dy * dy) / diag;
        const float dat  = fatan_pos(t3 / (t4 + 1e-7f)) - fatan_pos(bw / (bh + 1e-7f));
        const float vv   = 0.40528473456f * dat * dat;   // 4/pi^2
        const float alpha = vv / (1.0f - iou + vv + 1e-7f);
        s_ciou += diou + alpha * vv;

        // ---- box regression ----
        const float lw = __logf(1e-16f + t3 / aw);
        const float lh = __logf(1e-16f + t4 / ah);
        const float d1 = sx - t1, d2 = sy - t2, d3 = p3 - lw, d4 = p4 - lh;
        s_box += d1 * d1 + d2 * d2 + d3 * d3 + d4 * d4;

        // ---- class NLL: log-softmax over channels 5..84 ----
        const float c0 = (lane >= 5) ? v0 : -FLT_MAX;
        const float m  = warp_max(fmaxf(fmaxf(c0, v1), v2));
        float e = 0.0f;
        if (lane >= 5) e += fast_exp2(fmaxf((v0 - m) * LOG2E, -30.0f));
        e += fast_exp2(fmaxf((v1 - m) * LOG2E, -30.0f));
        if (lane < 21) e += fast_exp2(fmaxf((v2 - m) * LOG2E, -30.0f));
        const float Z = warp_sum(e);

        const int lch = 5 + (int)t5;
        const float x0 = __shfl_sync(0xffffffffu, v0, lch & 31);
        const float x1 = __shfl_sync(0xffffffffu, v1, lch & 31);
        const float x2 = __shfl_sync(0xffffffffu, v2, lch & 31);
        const float xl = (lch < 32) ? x0 : ((lch < 64) ? x1 : x2);

        s_cls += (m + __logf(Z)) - xl;
    }

    // block reduction (warp-uniform values; lane 0 contributes)
    __shared__ float sm[4][8];
    const int wib = threadIdx.x >> 5;
    if (lane == 0) {
        sm[0][wib] = s_obj; sm[1][wib] = s_ciou;
        sm[2][wib] = s_box; sm[3][wib] = s_cls;
    }
    __syncthreads();
    if (threadIdx.x < 4) {
        float s = 0.f;
        const int nw = blockDim.x >> 5;
        for (int w = 0; w < nw; w++) s += sm[threadIdx.x][w];
        atomicAdd(&g_acc[2 + ((threadIdx.x == 0) ? 0 : (threadIdx.x + 1))], (double)s);
        // map: 0->g_acc[2] obj, 1->g_acc[4] ciou, 2->g_acc[5] box, 3->g_acc[6] cls
    }
}

// Reads accumulators, writes scalar loss, resets state for next replay.
__global__ void finalize_kernel(float* __restrict__ out, int ncells) {
    if (threadIdx.x == 0) {
        const double nobj   = (double)g_nobj;
        const double cobj   = fmax(nobj, 1.0);
        const double cnoobj = fmax((double)ncells - nobj, 1.0);
        const double noobj  = g_acc[0] / cnoobj;
        const double objl   = g_acc[2] / cobj;
        const double cioul  = g_acc[4] / cobj;
        const double boxl   = (g_acc[5] / cobj) * 0.25;
        const double clsl   = g_acc[6] / cobj;
        out[0] = (float)(10.0 * boxl + 10.0 * objl + noobj + clsl + cioul);
#pragma unroll
        for (int i = 0; i < 7; i++) g_acc[i] = 0.0;
        g_nobj = 0;
    }
}

// Padding node so ncu's "-s 5 -c 1" (6th launch) lands on obj_kernel.
__global__ void pad_kernel() {}

extern "C" void kernel_launch(void* const* d_in, const int* in_sizes, int n_in,
                              void* d_out, int out_size) {
    int ip = 0, it = 1, ia = 2;
    long best = -1;
    for (int i = 0; i < n_in; i++) {
        if (in_sizes[i] == 6) ia = i;
        if ((long)in_sizes[i] > best) { best = in_sizes[i]; ip = i; }
    }
    for (int i = 0; i < n_in; i++) if (i != ip && i != ia) it = i;

    const float* pred = (const float*)d_in[ip];
    const float* tgt  = (const float*)d_in[it];
    const float* anc  = (const float*)d_in[ia];
    const int ncells  = in_sizes[ip] / NCH;

    const int nblkA = (ncells + 255) / 256;          // 1 chunk per warp
    scan_kernel<<<nblkA, 256>>>(pred, tgt, ncells);
    obj_kernel<<<4096, 256>>>(pred, tgt, anc);       // ~1 obj cell per warp
    finalize_kernel<<<1, 32>>>((float*)d_out, ncells);
    pad_kernel<<<1, 32>>>();
}

// round 9
// speedup vs baseline: 1.9457x; 1.1889x over previous
#include <cuda_runtime.h>
#include <math.h>
#include <float.h>

#define NCH 85
#define NTC 6
#define SS  (52 * 52)
#define LOG2E 1.44269504088896340736f
#define MAXCELLS 262144
#define OBJ_BLOCKS 1024

// g_acc: [0]=sum_noobj [2]=sum_obj [4]=sum_ciou [5]=sum_box [6]=sum_cls
// all __device__ state is zero at load and reset by the last obj block.
__device__ double g_acc[7];
__device__ int    g_nobj;
__device__ unsigned int g_done;
__device__ int    g_idx[MAXCELLS];

__device__ __forceinline__ float warp_max(float v) {
#pragma unroll
    for (int o = 16; o; o >>= 1) v = fmaxf(v, __shfl_xor_sync(0xffffffffu, v, o));
    return v;
}
__device__ __forceinline__ float warp_sum(float v) {
#pragma unroll
    for (int o = 16; o; o >>= 1) v += __shfl_xor_sync(0xffffffffu, v, o);
    return v;
}

// FFMA-pipe exp2 for x in [-30, 0]: magic-number round + degree-5 poly.
__device__ __forceinline__ float fast_exp2(float x) {
    float r  = x + 12582912.0f;                 // 1.5 * 2^23
    int   ik = __float_as_int(r) - 0x4B400000;
    float f  = x - (r - 12582912.0f);           // f in [-0.5, 0.5]
    float p  = 1.3333558e-3f;
    p = fmaf(p, f, 9.6181291e-3f);
    p = fmaf(p, f, 5.5504109e-2f);
    p = fmaf(p, f, 2.4022651e-1f);
    p = fmaf(p, f, 6.9314718e-1f);
    p = fmaf(p, f, 1.0f);
    return p * __int_as_float((ik + 127) << 23);
}

// atan(x) for x > 0: range-reduce to [0,1], 6-term minimax (abs err ~2e-7).
__device__ __forceinline__ float fatan_pos(float x) {
    const bool big = (x > 1.0f);
    const float t = big ? __fdividef(1.0f, x) : x;
    const float s = t * t;
    float p = -1.1721200e-2f;
    p = fmaf(p, s,  5.2653322e-2f);
    p = fmaf(p, s, -1.1643287e-1f);
    p = fmaf(p, s,  1.9354346e-1f);
    p = fmaf(p, s, -3.3262347e-1f);
    p = fmaf(p, s,  9.9997726e-1f);
    const float r = t * p;
    return big ? (1.57079632679f - r) : r;
}

__device__ __forceinline__ float sigmoidf_(float x) {
    return 1.0f / (1.0f + __expf(-x));
}

// ─────────────── Phase A: stream noobj + block-aggregated compaction ──────
__global__ __launch_bounds__(256)
void scan_kernel(const float* __restrict__ pred,
                 const float* __restrict__ tgt,
                 int ncells) {
    const int lane = threadIdx.x & 31;
    const int wib  = threadIdx.x >> 5;
    const int c    = blockIdx.x * 256 + threadIdx.x;
    const bool valid = (c < ncells);

    const float t0  = valid ? __ldg(tgt + (size_t)c * NTC) : -1.0f;
    const float p0l = valid ? __ldg(pred + (size_t)c * NCH) : 0.0f;

    // noobj BCE(p0, 0), per-thread
    float s_noobj = 0.f;
    if (t0 == 0.0f)
        s_noobj = fmaxf(p0l, 0.0f) + __logf(1.0f + __expf(-fabsf(p0l)));

    // warp-level obj mask
    const unsigned om  = __ballot_sync(0xffffffffu, t0 == 1.0f);
    const int wcount   = __popc(om);

    __shared__ int   wcnt[8];
    __shared__ int   blk_base;
    __shared__ float sn[8];

    s_noobj = warp_sum(s_noobj);
    if (lane == 0) { wcnt[wib] = wcount; sn[wib] = s_noobj; }
    __syncthreads();

    // thread 0: exclusive scan over 8 warp counts + ONE atomic for the block
    if (threadIdx.x == 0) {
        int tot = 0;
#pragma unroll
        for (int w = 0; w < 8; w++) { int t = wcnt[w]; wcnt[w] = tot; tot += t; }
        blk_base = tot ? atomicAdd(&g_nobj, tot) : 0;

        float s = 0.f;
#pragma unroll
        for (int w = 0; w < 8; w++) s += sn[w];
        atomicAdd(&g_acc[0], (double)s);
    }
    __syncthreads();

    if (t0 == 1.0f) {
        const int pos = blk_base + wcnt[wib] + __popc(om & ((1u << lane) - 1u));
        g_idx[pos] = c;
    }
}

// ───────── Phase B: dense obj cells + last-block finalize ─────────────────
__global__ __launch_bounds__(256)
void obj_kernel(const float* __restrict__ pred,
                const float* __restrict__ tgt,
                const float* __restrict__ anc,
                int ncells, float* __restrict__ out) {
    const int lane   = threadIdx.x & 31;
    const int gwarp  = (blockIdx.x * blockDim.x + threadIdx.x) >> 5;
    const int nwarps = (gridDim.x * blockDim.x) >> 5;
    const int nobj   = g_nobj;

    const float a0w = __ldg(anc + 0), a0h = __ldg(anc + 1);
    const float a1w = __ldg(anc + 2), a1h = __ldg(anc + 3);
    const float a2w = __ldg(anc + 4), a2h = __ldg(anc + 5);

    float s_obj = 0.f, s_ciou = 0.f, s_box = 0.f, s_cls = 0.f;

    for (int i = gwarp; i < nobj; i += nwarps) {
        const int cell = g_idx[i];
        const float* p = pred + (size_t)cell * NCH;
        const float* t = tgt  + (size_t)cell * NTC;

        float v0 = __ldg(p + lane);
        float v1 = __ldg(p + 32 + lane);
        float v2 = (lane < 21) ? __ldg(p + 64 + lane) : -FLT_MAX;
        const float2 t01 = __ldg((const float2*)(t + 0));
        const float2 t23 = __ldg((const float2*)(t + 2));
        const float2 t45 = __ldg((const float2*)(t + 4));
        const float t1 = t01.y;
        const float t2 = t23.x, t3 = t23.y;
        const float t4 = t45.x, t5 = t45.y;

        const float p0 = __shfl_sync(0xffffffffu, v0, 0);
        const float p1 = __shfl_sync(0xffffffffu, v0, 1);
        const float p2 = __shfl_sync(0xffffffffu, v0, 2);
        const float p3 = __shfl_sync(0xffffffffu, v0, 3);
        const float p4 = __shfl_sync(0xffffffffu, v0, 4);

        const int a = (cell / SS) % 3;
        const float aw = (a == 0) ? a0w : ((a == 1) ? a1w : a2w);
        const float ah = (a == 0) ? a0h : ((a == 1) ? a1h : a2h);

        const float sx = sigmoidf_(p1);
        const float sy = sigmoidf_(p2);
        const float bw = __expf(p3) * aw;
        const float bh = __expf(p4) * ah;

        // ---- midpoint IoU (bce target) ----
        const float b1x1 = sx - 0.5f * bw, b1x2 = sx + 0.5f * bw;
        const float b1y1 = sy - 0.5f * bh, b1y2 = sy + 0.5f * bh;
        const float b2x1 = t1 - 0.5f * t3, b2x2 = t1 + 0.5f * t3;
        const float b2y1 = t2 - 0.5f * t4, b2y2 = t2 + 0.5f * t4;
        const float iw = fmaxf(fminf(b1x2, b2x2) - fmaxf(b1x1, b2x1), 0.0f);
        const float ih = fmaxf(fminf(b1y2, b2y2) - fmaxf(b1y1, b2y1), 0.0f);
        const float inter = iw * ih;
        const float area1 = fabsf(bw * bh);
        const float area2 = fabsf(t3 * t4);
        const float iou_m = inter / (area1 + area2 - inter + 1e-6f);

        s_obj += fmaxf(p0, 0.0f) - p0 * iou_m + __logf(1.0f + __expf(-fabsf(p0)));

        // ---- CIoU ----
        const float uni  = bw * bh + t3 * t4 - inter;
        const float iou  = inter / (uni + 1e-7f);
        const float cw   = fmaxf(b1x2, b2x2) - fminf(b1x1, b2x1);
        const float chh  = fmaxf(b1y2, b2y2) - fminf(b1y1, b2y1);
        const float diag = cw * cw + chh * chh + 1e-7f;
        const float dx   = sx - t1;
        const float dy   = sy - t2;
        const float diou = 1.0f - iou + (dx * dx + dy * dy) / diag;
        const float dat  = fatan_pos(t3 / (t4 + 1e-7f)) - fatan_pos(bw / (bh + 1e-7f));
        const float vv   = 0.40528473456f * dat * dat;   // 4/pi^2
        const float alpha = vv / (1.0f - iou + vv + 1e-7f);
        s_ciou += diou + alpha * vv;

        // ---- box regression ----
        const float lw = __logf(1e-16f + t3 / aw);
        const float lh = __logf(1e-16f + t4 / ah);
        const float d1 = sx - t1, d2 = sy - t2, d3 = p3 - lw, d4 = p4 - lh;
        s_box += d1 * d1 + d2 * d2 + d3 * d3 + d4 * d4;

        // ---- class NLL: log-softmax over channels 5..84 ----
        const float c0 = (lane >= 5) ? v0 : -FLT_MAX;
        const float m  = warp_max(fmaxf(fmaxf(c0, v1), v2));
        float e = 0.0f;
        if (lane >= 5) e += fast_exp2(fmaxf((v0 - m) * LOG2E, -30.0f));
        e += fast_exp2(fmaxf((v1 - m) * LOG2E, -30.0f));
        if (lane < 21) e += fast_exp2(fmaxf((v2 - m) * LOG2E, -30.0f));
        const float Z = warp_sum(e);

        const int lch = 5 + (int)t5;
        const float x0 = __shfl_sync(0xffffffffu, v0, lch & 31);
        const float x1 = __shfl_sync(0xffffffffu, v1, lch & 31);
        const float x2 = __shfl_sync(0xffffffffu, v2, lch & 31);
        const float xl = (lch < 32) ? x0 : ((lch < 64) ? x1 : x2);

        s_cls += (m + __logf(Z)) - xl;
    }

    // block reduction -> atomics
    __shared__ float sm[4][8];
    const int wib = threadIdx.x >> 5;
    if (lane == 0) {
        sm[0][wib] = s_obj; sm[1][wib] = s_ciou;
        sm[2][wib] = s_box; sm[3][wib] = s_cls;
    }
    __syncthreads();
    if (threadIdx.x < 4) {
        float s = 0.f;
        const int nw = blockDim.x >> 5;
        for (int w = 0; w < nw; w++) s += sm[threadIdx.x][w];
        static const int map[4] = {2, 4, 5, 6};
        atomicAdd(&g_acc[map[threadIdx.x]], (double)s);
    }
    __threadfence();

    // last-block finalize + state reset
    __shared__ int is_last;
    if (threadIdx.x == 0) {
        unsigned prev = atomicAdd(&g_done, 1u);
        is_last = (prev == gridDim.x - 1u) ? 1 : 0;
    }
    __syncthreads();
    if (is_last && threadIdx.x == 0) {
        const double nobjd  = (double)nobj;
        const double cobj   = fmax(nobjd, 1.0);
        const double cnoobj = fmax((double)ncells - nobjd, 1.0);
        const double noobj  = g_acc[0] / cnoobj;
        const double objl   = g_acc[2] / cobj;
        const double cioul  = g_acc[4] / cobj;
        const double boxl   = (g_acc[5] / cobj) * 0.25;
        const double clsl   = g_acc[6] / cobj;
        out[0] = (float)(10.0 * boxl + 10.0 * objl + noobj + clsl + cioul);
#pragma unroll
        for (int k = 0; k < 7; k++) g_acc[k] = 0.0;
        g_nobj = 0;
        __threadfence();
        g_done = 0;
    }
}

extern "C" void kernel_launch(void* const* d_in, const int* in_sizes, int n_in,
                              void* d_out, int out_size) {
    int ip = 0, it = 1, ia = 2;
    long best = -1;
    for (int i = 0; i < n_in; i++) {
        if (in_sizes[i] == 6) ia = i;
        if ((long)in_sizes[i] > best) { best = in_sizes[i]; ip = i; }
    }
    for (int i = 0; i < n_in; i++) if (i != ip && i != ia) it = i;

    const float* pred = (const float*)d_in[ip];
    const float* tgt  = (const float*)d_in[it];
    const float* anc  = (const float*)d_in[ia];
    const int ncells  = in_sizes[ip] / NCH;

    const int nblkA = (ncells + 255) / 256;   // exact fit: 1 cell per thread
    scan_kernel<<<nblkA, 256>>>(pred, tgt, ncells);
    obj_kernel<<<OBJ_BLOCKS, 256>>>(pred, tgt, anc, ncells, (float*)d_out);
}